// round 9
// baseline (speedup 1.0000x reference)
#include <cuda_runtime.h>
#include <math.h>

#define BB 16
#define HW 65536            // 256*256
#define NPIX (BB*HW)        // 1048576
#define WPR 8               // u32 words per row
#define WPS 2048            // words per sample
#define NWORDS 32768
#define WLCAP 65536

#define TPB1 256
#define NB1 1024            // 1024 px per block
#define TPB2 128
#define NB2 (NWORDS/TPB2)   // 256

// ---- device scratch (allocation-free). Reset by K2's last block. ----
__device__ unsigned g_posbits[NWORDS];
__device__ unsigned g_t1bits[NWORDS];
__device__ double g_ce;
__device__ int    g_hard_i, g_t_i, g_inter_i;
__device__ double g_res[BB];
__device__ int    g_haspos[BB];
__device__ int    g_hasneg[BB];
__device__ unsigned g_ticket;
__device__ int    g_wl_n;
__device__ int    g_wl[WLCAP];

// ---------------------------------------------------------------------------
// Exact fallback (P ~ 2^-24 per target pixel; runs in K2's last block only)
// ---------------------------------------------------------------------------
__device__ __forceinline__ int row_mindx(const unsigned* __restrict__ row, int j, unsigned inv) {
    int wj = j >> 5, off = j & 31;
    int best = 30000;
    unsigned m = (row[wj] ^ inv) >> off;
    if (m) best = __ffs(m) - 1;
    else {
        for (int w = wj + 1; w < WPR; ++w) {
            unsigned x = row[w] ^ inv;
            if (x) { best = 32 * (w - wj) - off + __ffs(x) - 1; break; }
        }
    }
    unsigned ml = (row[wj] ^ inv) << (31 - off);
    if (ml) { int d = __clz(ml); best = min(best, d); }
    else {
        for (int w = wj - 1; w >= 0; --w) {
            unsigned x = row[w] ^ inv;
            if (x) { int d = j - (32 * w + 31 - __clz(x)); best = min(best, d); break; }
        }
    }
    return best;
}

__device__ double fb_contrib(const unsigned* __restrict__ bp, int i, int j, int mybit,
                             int haspos, int hasneg) {
    float d;
    if (!haspos || !hasneg) {
        d = 1.0e9f;                      // reference BIG
    } else {
        unsigned inv = mybit ? 0xffffffffu : 0u;
        int best2 = 1 << 30;
        for (int dy = 0; dy < 256; ++dy) {
            int dy2 = dy * dy;
            if (dy2 >= best2) break;
            int up = i - dy, dn = i + dy;
            if (up >= 0) {
                int dx = row_mindx(bp + up * WPR, j, inv);
                int d2 = dy2 + dx * dx;
                if (d2 < best2) best2 = d2;
            }
            if (dy && dn < 256) {
                int dx = row_mindx(bp + dn * WPR, j, inv);
                int d2 = dy2 + dx * dx;
                if (d2 < best2) best2 = d2;
            }
        }
        d = sqrtf((float)best2);
    }
    return mybit ? -(double)(d - 1.0f) : (double)d;
}

// ---------------------------------------------------------------------------
// K1: streaming prep. Lane-strided pixels; ballots build bitboard words.
// ---------------------------------------------------------------------------
__global__ __launch_bounds__(TPB1)
void k_prep(const float* __restrict__ inp, const int* __restrict__ tgt) {
    int tid = threadIdx.x, w = tid >> 5, l = tid & 31;
    int base = blockIdx.x * 1024 + w * 128;   // warp's 128-px span
    int s    = blockIdx.x >> 6;               // 64 blocks per sample
    int hwb  = base & 65535;

    const float* c0 = inp + (size_t)(s * 2) * HW;
    const float* c1 = c0 + HW;
    const int*   tg = tgt + (s << 16);

    float ces = 0.0f;
    int hard = 0, tcnt = 0, inter = 0;
    unsigned anyp = 0u, alln = 0xffffffffu;

    #pragma unroll
    for (int it = 0; it < 4; ++it) {
        int hw = hwb + it * 32 + l;
        float x0 = __ldg(c0 + hw);
        float x1 = __ldg(c1 + hw);
        int   t  = __ldg(tg + hw);
        float d  = x1 - x0;
        float lse = fmaxf(x0, x1) + __logf(1.0f + __expf(-fabsf(d)));
        ces += lse - ((t == 1) ? x1 : x0);

        unsigned bp_ = __ballot_sync(0xffffffffu, x1 >  x0);
        unsigned bh  = __ballot_sync(0xffffffffu, x1 >= x0);
        unsigned bt  = __ballot_sync(0xffffffffu, t == 1);
        hard  += __popc(bh);
        tcnt  += __popc(bt);
        inter += __popc(bh & bt);
        anyp  |= bp_;
        alln  &= bp_;
        if (l == it) {
            int wi = (base >> 5) + it;
            g_posbits[wi] = bp_;
            g_t1bits[wi]  = bt;
        }
    }

    #pragma unroll
    for (int off = 16; off > 0; off >>= 1)
        ces += __shfl_xor_sync(0xffffffffu, ces, off);

    __shared__ float sce[8];
    __shared__ int   scnt[8], sfl[8];
    unsigned cnt = (unsigned)hard | ((unsigned)tcnt << 10) | ((unsigned)inter << 20);
    if (l == 0) {
        sce[w]  = ces;
        scnt[w] = (int)cnt;
        sfl[w]  = (anyp ? 1 : 0) | ((alln != 0xffffffffu) ? 2 : 0);
    }
    __syncthreads();
    if (tid == 0) {
        float bce = 0.0f; int bh = 0, bt2 = 0, bi = 0, bfl = 0;
        #pragma unroll
        for (int k = 0; k < 8; ++k) {
            bce += sce[k];
            unsigned c = (unsigned)scnt[k];
            bh += (int)(c & 1023u); bt2 += (int)((c >> 10) & 1023u); bi += (int)(c >> 20);
            bfl |= sfl[k];
        }
        atomicAdd(&g_ce, (double)bce);
        atomicAdd(&g_hard_i,  bh);
        atomicAdd(&g_t_i,     bt2);
        atomicAdd(&g_inter_i, bi);
        if (bfl & 1) g_haspos[s] = 1;
        if (bfl & 2) g_hasneg[s] = 1;
    }
}

// ---------------------------------------------------------------------------
// K2: 5x5 bit-parallel boundary from L2-resident bitboards + finalize.
// ---------------------------------------------------------------------------
__global__ __launch_bounds__(TPB2)
void k_bnd(float* __restrict__ out, int out_size) {
    int tid = threadIdx.x;
    int tw  = blockIdx.x * TPB2 + tid;
    int b   = tw >> 11;              // 16 blocks per sample
    int w   = tw & 2047;
    int i   = w >> 3, wc = w & 7;

    const unsigned* __restrict__ bp = g_posbits + b * WPS;
    const unsigned* __restrict__ tp = g_t1bits  + b * WPS;

    unsigned P  = __ldg(bp + i * WPR + wc);
    unsigned T1 = __ldg(tp + i * WPR + wc);

    unsigned lm1 = (wc == 0) ? 0xfffffffeu : 0xffffffffu;
    unsigned rm1 = (wc == 7) ? 0x7fffffffu : 0xffffffffu;
    unsigned lm2 = (wc == 0) ? 0xfffffffcu : 0xffffffffu;
    unsigned rm2 = (wc == 7) ? 0x3fffffffu : 0xffffffffu;
    unsigned vu1 = (i >= 1)   ? 0xffffffffu : 0u;
    unsigned vu2 = (i >= 2)   ? 0xffffffffu : 0u;
    unsigned vd1 = (i <= 254) ? 0xffffffffu : 0u;
    unsigned vd2 = (i <= 253) ? 0xffffffffu : 0u;
    int iu1 = max(i - 1, 0), iu2 = max(i - 2, 0);
    int id1 = min(i + 1, 255), id2 = min(i + 2, 255);

    #define ROWX(r, XM, X1L, X1R, X2L, X2R) {                        \
        unsigned Lw = (wc > 0) ? __ldg(bp + (r) * WPR + wc - 1) : 0u;\
        unsigned Mw = __ldg(bp + (r) * WPR + wc);                    \
        unsigned Rw = (wc < 7) ? __ldg(bp + (r) * WPR + wc + 1) : 0u;\
        XM  = Mw ^ P;                                                \
        X1L = __funnelshift_l(Lw, Mw, 1) ^ P;                        \
        X1R = __funnelshift_r(Mw, Rw, 1) ^ P;                        \
        X2L = __funnelshift_l(Lw, Mw, 2) ^ P;                        \
        X2R = __funnelshift_r(Mw, Rw, 2) ^ P; }

    unsigned m0, l10, r10, l20, r20;      ROWX(i,   m0,  l10,  r10,  l20,  r20)
    unsigned mu1, l1u1, r1u1, l2u1, r2u1; ROWX(iu1, mu1, l1u1, r1u1, l2u1, r2u1)
    unsigned md1, l1d1, r1d1, l2d1, r2d1; ROWX(id1, md1, l1d1, r1d1, l2d1, r2d1)
    unsigned mu2, l1u2, r1u2, l2u2, r2u2; ROWX(iu2, mu2, l1u2, r1u2, l2u2, r2u2)
    unsigned md2, l1d2, r1d2, l2d2, r2d2; ROWX(id2, md2, l1d2, r1d2, l2d2, r2d2)
    #undef ROWX

    unsigned D1 = (l10 & lm1) | (r10 & rm1) | (mu1 & vu1) | (md1 & vd1);
    unsigned D2 = (((l1u1 & lm1) | (r1u1 & rm1)) & vu1)
                | (((l1d1 & lm1) | (r1d1 & rm1)) & vd1);
    unsigned D4 = (l20 & lm2) | (r20 & rm2) | (mu2 & vu2) | (md2 & vd2);
    unsigned D5 = (((l2u1 & lm2) | (r2u1 & rm2)) & vu1)
                | (((l2d1 & lm2) | (r2d1 & rm2)) & vd1)
                | (((l1u2 & lm1) | (r1u2 & rm1)) & vu2)
                | (((l1d2 & lm1) | (r1d2 & rm1)) & vd2);
    unsigned D8 = (((l2u2 & lm2) | (r2u2 & rm2)) & vu2)
                | (((l2d2 & lm2) | (r2d2 & rm2)) & vd2);

    unsigned A1m = D1 & T1;
    unsigned R2m = T1 & ~D1;   unsigned A2m = D2 & R2m;
    unsigned R4m = R2m & ~D2;  unsigned A4m = D4 & R4m;
    unsigned R5m = R4m & ~D4;  unsigned A5m = D5 & R5m;
    unsigned R8m = R5m & ~D5;  unsigned A8m = D8 & R8m;
    unsigned U   = R8m & ~D8;

    const float S2 = 1.41421354f;
    const float S5 = 2.23606801f;
    const float S8 = 2.82842708f;

    float contrib;
    contrib  = (float)__popc(A1m & ~P);
    contrib += (float)__popc(A2m & ~P) * S2 - (float)__popc(A2m & P) * (S2 - 1.0f);
    contrib += (float)__popc(A4m & ~P) * 2.0f - (float)__popc(A4m & P) * 1.0f;
    contrib += (float)__popc(A5m & ~P) * S5 - (float)__popc(A5m & P) * (S5 - 1.0f);
    contrib += (float)__popc(A8m & ~P) * S8 - (float)__popc(A8m & P) * (S8 - 1.0f);

    while (U) {   // ~never: defer to worklist for the final block
        int jb = __ffs(U) - 1; U &= U - 1;
        int j = wc * 32 + jb;
        int mybit = (P >> jb) & 1;
        int slot = atomicAdd(&g_wl_n, 1);
        if (slot < WLCAP)
            g_wl[slot] = (b << 17) | (i << 9) | (j << 1) | mybit;
    }

    #pragma unroll
    for (int off = 16; off > 0; off >>= 1)
        contrib += __shfl_xor_sync(0xffffffffu, contrib, off);
    __shared__ float s_c[4];
    int wid = tid >> 5;
    if ((tid & 31) == 0) s_c[wid] = contrib;
    __syncthreads();

    __shared__ bool s_last;
    if (tid == 0) {
        atomicAdd(&g_res[b], (double)(s_c[0] + s_c[1] + s_c[2] + s_c[3]));
        __threadfence();
        unsigned tk = atomicAdd(&g_ticket, 1u);
        s_last = (tk == NB2 - 1);
    }
    __syncthreads();

    if (s_last) {
        if (tid == 0) __threadfence();
        __syncthreads();
        int n = g_wl_n; if (n > WLCAP) n = WLCAP;
        for (int k = tid; k < n; k += TPB2) {
            int e = g_wl[k];
            int es = e >> 17, ei = (e >> 9) & 255, ej = (e >> 1) & 255, eb = e & 1;
            double v = fb_contrib(g_posbits + es * WPS, ei, ej, eb,
                                  g_haspos[es], g_hasneg[es]);
            atomicAdd(&g_res[es], v);
        }
        __syncthreads();
        if (tid == 0) {
            double ce = g_ce / (double)NPIX;
            double dice = 1.0 - (2.0 * (double)g_inter_i + 1.0)
                              / ((double)g_hard_i + (double)g_t_i + 1.0);
            double lb = 0.0;
            #pragma unroll
            for (int q = 0; q < BB; ++q)
                if (g_haspos[q]) lb += g_res[q] / (double)HW;
            float r = (float)(ce + dice + lb * lb);
            for (int k = 0; k < out_size; ++k) out[k] = r;

            g_ce = 0.0; g_hard_i = 0; g_t_i = 0; g_inter_i = 0;
            #pragma unroll
            for (int q = 0; q < BB; ++q) { g_res[q] = 0.0; g_haspos[q] = 0; g_hasneg[q] = 0; }
            g_ticket = 0u; g_wl_n = 0;
        }
    }
}

extern "C" void kernel_launch(void* const* d_in, const int* in_sizes, int n_in,
                              void* d_out, int out_size) {
    const float* inputs  = (const float*)d_in[0];   // (16,2,256,256) f32
    const int*   targets = (const int*)  d_in[1];   // (16,256,256)   i32
    k_prep<<<NB1, TPB1>>>(inputs, targets);
    k_bnd<<<NB2, TPB2>>>((float*)d_out, out_size);
}

// round 10
// speedup vs baseline: 1.1569x; 1.1569x over previous
#include <cuda_runtime.h>
#include <math.h>

#define BB 16
#define HW 65536            // 256*256
#define NPIX (BB*HW)        // 1048576
#define WPR 8               // u32 words per row
#define WPS 2048            // words per sample
#define NWORDS 32768
#define NB 512              // 16 samples * 32 row-groups (8 rows each)
#define TPB 256
#define WLCAP 65536

// ---- device scratch (allocation-free). Reset by final block each replay. ----
__device__ unsigned g_posbits[NWORDS];
__device__ double g_ce;
__device__ int    g_hard_i, g_t_i, g_inter_i;
__device__ double g_res[BB];
__device__ int    g_haspos[BB];
__device__ int    g_hasneg[BB];
__device__ unsigned g_ticket;
__device__ int    g_wl_n;
__device__ int    g_wl[WLCAP];

// ---------------------------------------------------------------------------
// Exact fallback (rare; runs in final block only)
// ---------------------------------------------------------------------------
__device__ __forceinline__ int row_mindx(const unsigned* __restrict__ row, int j, unsigned inv) {
    int wj = j >> 5, off = j & 31;
    int best = 30000;
    unsigned m = (row[wj] ^ inv) >> off;
    if (m) best = __ffs(m) - 1;
    else {
        for (int w = wj + 1; w < WPR; ++w) {
            unsigned x = row[w] ^ inv;
            if (x) { best = 32 * (w - wj) - off + __ffs(x) - 1; break; }
        }
    }
    unsigned ml = (row[wj] ^ inv) << (31 - off);
    if (ml) { int d = __clz(ml); best = min(best, d); }
    else {
        for (int w = wj - 1; w >= 0; --w) {
            unsigned x = row[w] ^ inv;
            if (x) { int d = j - (32 * w + 31 - __clz(x)); best = min(best, d); break; }
        }
    }
    return best;
}

__device__ double fb_contrib(const unsigned* __restrict__ bp, int i, int j, int mybit,
                             int haspos, int hasneg) {
    float d;
    if (!haspos || !hasneg) {
        d = 1.0e9f;                      // reference BIG
    } else {
        unsigned inv = mybit ? 0xffffffffu : 0u;
        int best2 = 1 << 30;
        for (int dy = 0; dy < 256; ++dy) {
            int dy2 = dy * dy;
            if (dy2 >= best2) break;
            int up = i - dy, dn = i + dy;
            if (up >= 0) {
                int dx = row_mindx(bp + up * WPR, j, inv);
                int d2 = dy2 + dx * dx;
                if (d2 < best2) best2 = d2;
            }
            if (dy && dn < 256) {
                int dx = row_mindx(bp + dn * WPR, j, inv);
                int d2 = dy2 + dx * dx;
                if (d2 < best2) best2 = d2;
            }
        }
        d = sqrtf((float)best2);
    }
    return mybit ? -(double)(d - 1.0f) : (double)d;
}

// ---------------------------------------------------------------------------
// Fused kernel: ballot-native prep + halo, SMEM 5x5 phase 2, ticket finalize.
// ---------------------------------------------------------------------------
__global__ __launch_bounds__(TPB)
void k_fused(const float* __restrict__ inp, const int* __restrict__ tgt,
             float* __restrict__ out, int out_size) {
    __shared__ unsigned sh_pw[12 * 8];   // rows r0-2 .. r0+9 as u32 words
    __shared__ unsigned sh_tw[8 * 8];    // main rows t1 words
    __shared__ float  sce[8];
    __shared__ int    scnt[8], sfl[8];
    __shared__ float  s_c[2];
    __shared__ bool   s_last;

    int tid = threadIdx.x, w = tid >> 5, l = tid & 31;
    int blk = blockIdx.x;
    int s   = blk >> 5;            // sample
    int r0  = (blk & 31) << 3;     // first main row
    int row = r0 + w;              // this warp's row

    const float* __restrict__ c0 = inp + (size_t)(s * 2) * HW;
    const float* __restrict__ c1 = c0 + HW;
    const int*   __restrict__ tg = tgt + (s << 16);

    // ---------------- Phase 1: main rows (warp = row, 8 ballots) -----------
    float ces = 0.0f;
    int hard = 0, tcnt = 0, inter = 0;
    unsigned anyp = 0u, alln = 0xffffffffu;
    int rowbase = row << 8;

    #pragma unroll
    for (int it = 0; it < 8; ++it) {
        int hw = rowbase + it * 32 + l;
        float x0 = c0[hw];
        float x1 = c1[hw];
        int   t  = tg[hw];
        float lse = fmaxf(x0, x1) + __logf(1.0f + __expf(-fabsf(x1 - x0)));
        ces += lse - ((t == 1) ? x1 : x0);

        unsigned bp_ = __ballot_sync(0xffffffffu, x1 >  x0);
        unsigned bh  = __ballot_sync(0xffffffffu, x1 >= x0);
        unsigned bt  = __ballot_sync(0xffffffffu, t == 1);
        hard  += __popc(bh);
        tcnt  += __popc(bt);
        inter += __popc(bh & bt);
        anyp  |= bp_;
        alln  &= bp_;
        if (l == it) {
            sh_pw[(w + 2) * 8 + it] = bp_;
            sh_tw[w * 8 + it]       = bt;
        }
    }

    // ---------------- halo rows: 4 warp-uniform ballot iterations ----------
    #pragma unroll
    for (int q = 0; q < 4; ++q) {
        int hidx = w * 4 + q;                 // 0..31
        int hrow = hidx >> 3, grp = hidx & 7;
        int habs = (hrow < 2) ? (r0 - 2 + hrow) : (r0 + 6 + hrow);   // hrow 2->r0+8, 3->r0+9
        int row12 = (hrow < 2) ? hrow : (8 + hrow);                  // 0,1,10,11
        unsigned hb = 0u;
        if (habs >= 0 && habs <= 255) {       // warp-uniform condition
            int hw = (habs << 8) + grp * 32 + l;
            float x0 = c0[hw];
            float x1 = c1[hw];
            hb = __ballot_sync(0xffffffffu, x1 > x0);
        }
        if (l == 0) sh_pw[row12 * 8 + grp] = hb;
    }

    // ---------------- reductions -------------------------------------------
    #pragma unroll
    for (int off = 16; off > 0; off >>= 1)
        ces += __shfl_xor_sync(0xffffffffu, ces, off);
    if (l == 0) {
        sce[w]  = ces;
        scnt[w] = (int)((unsigned)hard | ((unsigned)tcnt << 10) | ((unsigned)inter << 20));
        sfl[w]  = (anyp ? 1 : 0) | ((alln != 0xffffffffu) ? 2 : 0);
    }
    __syncthreads();

    if (tid == 0) {
        float bce = 0.0f; int bh = 0, bt = 0, bi = 0, bfl = 0;
        #pragma unroll
        for (int k = 0; k < 8; ++k) {
            bce += sce[k];
            unsigned c = (unsigned)scnt[k];
            bh += (int)(c & 1023u); bt += (int)((c >> 10) & 1023u); bi += (int)(c >> 20);
            bfl |= sfl[k];
        }
        atomicAdd(&g_ce, (double)bce);
        atomicAdd(&g_hard_i,  bh);
        atomicAdd(&g_t_i,     bt);
        atomicAdd(&g_inter_i, bi);
        if (bfl & 1) g_haspos[s] = 1;
        if (bfl & 2) g_hasneg[s] = 1;
    }

    // ---------------- Phase 2: 5x5 bit-parallel (64 threads) ---------------
    float contrib = 0.0f;
    if (tid < 64) {
        int wr = tid >> 3, wc = tid & 7;
        int i   = r0 + wr;
        int i12 = wr + 2;

        unsigned P  = sh_pw[i12 * 8 + wc];
        unsigned T1 = sh_tw[wr * 8 + wc];
        g_posbits[s * WPS + i * WPR + wc] = P;   // for worklist fallback only

        unsigned lm1 = (wc == 0) ? 0xfffffffeu : 0xffffffffu;
        unsigned rm1 = (wc == 7) ? 0x7fffffffu : 0xffffffffu;
        unsigned lm2 = (wc == 0) ? 0xfffffffcu : 0xffffffffu;
        unsigned rm2 = (wc == 7) ? 0x3fffffffu : 0xffffffffu;
        unsigned vu1 = (i >= 1)   ? 0xffffffffu : 0u;
        unsigned vu2 = (i >= 2)   ? 0xffffffffu : 0u;
        unsigned vd1 = (i <= 254) ? 0xffffffffu : 0u;
        unsigned vd2 = (i <= 253) ? 0xffffffffu : 0u;

        #define ROWX(r12, XM, X1L, X1R, X2L, X2R) {                      \
            unsigned Lw = (wc > 0) ? sh_pw[(r12) * 8 + wc - 1] : 0u;     \
            unsigned Mw = sh_pw[(r12) * 8 + wc];                         \
            unsigned Rw = (wc < 7) ? sh_pw[(r12) * 8 + wc + 1] : 0u;     \
            XM  = Mw ^ P;                                                \
            X1L = __funnelshift_l(Lw, Mw, 1) ^ P;                        \
            X1R = __funnelshift_r(Mw, Rw, 1) ^ P;                        \
            X2L = __funnelshift_l(Lw, Mw, 2) ^ P;                        \
            X2R = __funnelshift_r(Mw, Rw, 2) ^ P; }

        unsigned m0, l10, r10, l20, r20;      ROWX(i12,     m0,  l10,  r10,  l20,  r20)
        unsigned mu1, l1u1, r1u1, l2u1, r2u1; ROWX(i12 - 1, mu1, l1u1, r1u1, l2u1, r2u1)
        unsigned md1, l1d1, r1d1, l2d1, r2d1; ROWX(i12 + 1, md1, l1d1, r1d1, l2d1, r2d1)
        unsigned mu2, l1u2, r1u2, l2u2, r2u2; ROWX(i12 - 2, mu2, l1u2, r1u2, l2u2, r2u2)
        unsigned md2, l1d2, r1d2, l2d2, r2d2; ROWX(i12 + 2, md2, l1d2, r1d2, l2d2, r2d2)
        #undef ROWX

        unsigned D1 = (l10 & lm1) | (r10 & rm1) | (mu1 & vu1) | (md1 & vd1);
        unsigned D2 = (((l1u1 & lm1) | (r1u1 & rm1)) & vu1)
                    | (((l1d1 & lm1) | (r1d1 & rm1)) & vd1);
        unsigned D4 = (l20 & lm2) | (r20 & rm2) | (mu2 & vu2) | (md2 & vd2);
        unsigned D5 = (((l2u1 & lm2) | (r2u1 & rm2)) & vu1)
                    | (((l2d1 & lm2) | (r2d1 & rm2)) & vd1)
                    | (((l1u2 & lm1) | (r1u2 & rm1)) & vu2)
                    | (((l1d2 & lm1) | (r1d2 & rm1)) & vd2);
        unsigned D8 = (((l2u2 & lm2) | (r2u2 & rm2)) & vu2)
                    | (((l2d2 & lm2) | (r2d2 & rm2)) & vd2);

        unsigned A1m = D1 & T1;
        unsigned R2m = T1 & ~D1;   unsigned A2m = D2 & R2m;
        unsigned R4m = R2m & ~D2;  unsigned A4m = D4 & R4m;
        unsigned R5m = R4m & ~D4;  unsigned A5m = D5 & R5m;
        unsigned R8m = R5m & ~D5;  unsigned A8m = D8 & R8m;
        unsigned U   = R8m & ~D8;

        const float S2 = 1.41421354f;
        const float S5 = 2.23606801f;
        const float S8 = 2.82842708f;

        contrib  = (float)__popc(A1m & ~P);
        contrib += (float)__popc(A2m & ~P) * S2 - (float)__popc(A2m & P) * (S2 - 1.0f);
        contrib += (float)__popc(A4m & ~P) * 2.0f - (float)__popc(A4m & P) * 1.0f;
        contrib += (float)__popc(A5m & ~P) * S5 - (float)__popc(A5m & P) * (S5 - 1.0f);
        contrib += (float)__popc(A8m & ~P) * S8 - (float)__popc(A8m & P) * (S8 - 1.0f);

        while (U) {   // rare: defer to worklist for the final block
            int jb = __ffs(U) - 1; U &= U - 1;
            int j = wc * 32 + jb;
            int mybit = (P >> jb) & 1;
            int slot = atomicAdd(&g_wl_n, 1);
            if (slot < WLCAP)
                g_wl[slot] = (s << 17) | (i << 9) | (j << 1) | mybit;
        }

        #pragma unroll
        for (int off = 16; off > 0; off >>= 1)
            contrib += __shfl_xor_sync(0xffffffffu, contrib, off);
        if (tid == 0)  s_c[0] = contrib;
        if (tid == 32) s_c[1] = contrib;
    }
    __syncthreads();

    if (tid == 0) {
        atomicAdd(&g_res[s], (double)(s_c[0] + s_c[1]));
        __threadfence();
        unsigned tk = atomicAdd(&g_ticket, 1u);
        s_last = (tk == NB - 1);
    }
    __syncthreads();

    // ---------------- Final block: worklist + finalize ----------------------
    if (s_last) {
        if (tid == 0) __threadfence();
        __syncthreads();
        int n = g_wl_n; if (n > WLCAP) n = WLCAP;
        for (int k = tid; k < n; k += TPB) {
            int e = g_wl[k];
            int es = e >> 17, ei = (e >> 9) & 255, ej = (e >> 1) & 255, eb = e & 1;
            double v = fb_contrib(g_posbits + es * WPS, ei, ej, eb,
                                  g_haspos[es], g_hasneg[es]);
            atomicAdd(&g_res[es], v);
        }
        __syncthreads();
        if (tid == 0) {
            double ce = g_ce / (double)NPIX;
            double dice = 1.0 - (2.0 * (double)g_inter_i + 1.0)
                              / ((double)g_hard_i + (double)g_t_i + 1.0);
            double lb = 0.0;
            #pragma unroll
            for (int q = 0; q < BB; ++q)
                if (g_haspos[q]) lb += g_res[q] / (double)HW;
            float r = (float)(ce + dice + lb * lb);
            for (int k = 0; k < out_size; ++k) out[k] = r;

            g_ce = 0.0; g_hard_i = 0; g_t_i = 0; g_inter_i = 0;
            #pragma unroll
            for (int q = 0; q < BB; ++q) { g_res[q] = 0.0; g_haspos[q] = 0; g_hasneg[q] = 0; }
            g_ticket = 0u; g_wl_n = 0;
        }
    }
}

extern "C" void kernel_launch(void* const* d_in, const int* in_sizes, int n_in,
                              void* d_out, int out_size) {
    const float* inputs  = (const float*)d_in[0];   // (16,2,256,256) f32
    const int*   targets = (const int*)  d_in[1];   // (16,256,256)   i32
    k_fused<<<NB, TPB>>>(inputs, targets, (float*)d_out, out_size);
}